// round 12
// baseline (speedup 1.0000x reference)
#include <cuda_runtime.h>
#include <math.h>
#include <stdint.h>
#include <float.h>

#define BSZ 8
#define TT  8192
#define FF  1024
#define HH  256
#define OO  2
#define MTOK (BSZ * TT)   // 65536 tokens
#define NCHUNK 64

// ---- scratch (static device globals; no runtime allocation) ----
__device__ uint4  g_hb4[(size_t)MTOK * 32];   // 32 MB bf16 h, plain [m][256] (128 words/row)
__device__ float  g_logit[MTOK];
__device__ float2 g_stat[BSZ];
__device__ float  g_part[BSZ * NCHUNK * HH];
__device__ uint4  g_w1s[32 * 1024];           // 512 KB: W1 bf16 [kt2 32][n 256][kw 16]
__device__ uint4  g_wvs[16 * 512];            // 128 KB: Wv bf16 [blk 16][n 64][kw 32]
__device__ uint4  g_wus[16 * 512];            // 128 KB: Wu

// ---- helpers ----
__device__ __forceinline__ uint32_t pbf(float lo, float hi) {
    uint32_t r; asm("cvt.rn.bf16x2.f32 %0, %1, %2;" : "=r"(r) : "f"(hi), "f"(lo)); return r;
}
__device__ __forceinline__ float tanhfast(float x) {
    float y; asm("tanh.approx.f32 %0, %1;" : "=f"(y) : "f"(x)); return y;
}
__device__ __forceinline__ void mma16(float4& d, const uint32_t* a, uint32_t b0, uint32_t b1) {
    asm volatile("mma.sync.aligned.m16n8k16.row.col.f32.bf16.bf16.f32 "
        "{%0,%1,%2,%3}, {%4,%5,%6,%7}, {%8,%9}, {%0,%1,%2,%3};"
        : "+f"(d.x), "+f"(d.y), "+f"(d.z), "+f"(d.w)
        : "r"(a[0]), "r"(a[1]), "r"(a[2]), "r"(a[3]), "r"(b0), "r"(b1));
}
__device__ __forceinline__ void ldsm4(uint32_t& r0, uint32_t& r1, uint32_t& r2, uint32_t& r3,
                                      uint32_t addr) {
    asm volatile("ldmatrix.sync.aligned.m8n8.x4.shared.b16 {%0,%1,%2,%3}, [%4];"
        : "=r"(r0), "=r"(r1), "=r"(r2), "=r"(r3) : "r"(addr));
}
__device__ __forceinline__ uint32_t s2u(const void* p) {
    uint32_t a; asm("{ .reg .u64 t; cvta.to.shared.u64 t, %1; cvt.u32.u64 %0, t; }" : "=r"(a) : "l"(p));
    return a;
}
__device__ __forceinline__ void cpa16(uint32_t dst, const void* src) {
    asm volatile("cp.async.cg.shared.global [%0], [%1], 16;" :: "r"(dst), "l"(src));
}
__device__ __forceinline__ void cp_commit() { asm volatile("cp.async.commit_group;"); }
__device__ __forceinline__ void cp_wait0()  { asm volatile("cp.async.wait_group 0;"); }
__device__ __forceinline__ void cp_wait1()  { asm volatile("cp.async.wait_group 1;"); }
__device__ __forceinline__ void cp_wait2()  { asm volatile("cp.async.wait_group 2;"); }

// ============================================================================
// k1pre: W1 [1024,256] -> bf16 images [kt2 32][n 256][kw 16].
// word(kt2,n,kwi) packs (W1[kt2*32+2kwi][n], W1[..+1][n]).
// ============================================================================
__global__ __launch_bounds__(256)
void k1pre(const float* __restrict__ W1)
{
    const int kt2 = blockIdx.x, n = threadIdx.x;
    uint32_t* dst = (uint32_t*)g_w1s + kt2 * 4096 + n * 16;
    #pragma unroll
    for (int kwi = 0; kwi < 16; kwi++) {
        const int k = kt2 * 32 + 2 * kwi;
        dst[kwi] = pbf(W1[(size_t)k * HH + n], W1[(size_t)(k + 1) * HH + n]);
    }
}

// ============================================================================
// k2pre: Wv/Wu [256,256] -> bf16 images [blk=nb*4+kh][n 64][kw 32].
// ============================================================================
__global__ __launch_bounds__(256)
void k2pre(const float* __restrict__ Wv, const float* __restrict__ Wu)
{
    const int blk = blockIdx.x, tid = threadIdx.x;
    const int nb = blk >> 2, kh = blk & 3;
    const int n = tid & 63, kg = tid >> 6;
    uint32_t* dv = (uint32_t*)g_wvs + blk * 2048 + n * 32;
    uint32_t* du = (uint32_t*)g_wus + blk * 2048 + n * 32;
    #pragma unroll
    for (int j = 0; j < 8; j++) {
        const int kwi = kg * 8 + j;
        const int k = kh * 64 + 2 * kwi;
        const size_t o0 = (size_t)k * HH + nb * 64 + n;
        dv[kwi] = pbf(Wv[o0], Wv[o0 + HH]);
        du[kwi] = pbf(Wu[o0], Wu[o0 + HH]);
    }
}

// ============================================================================
// K1: h = relu(bags @ W1 + b1). CTA 128x256, 512 thr, K=32 stages, 4-slot
// cp.async. A raw fp32 -> bf16 [m][kw] (20w rows), B [n][kw] (20w rows),
// all fragments via ldmatrix.x4. Epilogue -> plain bf16 g_hb4 [m][128w].
// ============================================================================
#define K1_ASLOT (128 * 36)     // raw A words / slot
#define K1_BSLOT (256 * 20)     // B words / slot
#define K1_FBUF  (128 * 20)     // bf16 A words / buffer
#define K1_SMEM  ((4 * K1_ASLOT + 4 * K1_BSLOT + 2 * K1_FBUF) * 4)   // 176128 B
__global__ __launch_bounds__(512, 1)
void k1_gemm_relu(const float* __restrict__ A, const float* __restrict__ bias)
{
    extern __shared__ uint32_t sm1[];
    uint32_t* Araw = sm1;                       // [4][128][36] raw fp32
    uint32_t* Bst  = sm1 + 4 * K1_ASLOT;        // [4][256 n][20]
    uint32_t* bfA  = Bst + 4 * K1_BSLOT;        // [2][128 m][20]
    const uint32_t sAraw = s2u(Araw), sBst = s2u(Bst), sbfA = s2u(bfA);

    const int tid = threadIdx.x;
    const int lane = tid & 31, wid = tid >> 5;
    const int wm = wid & 3, wn = wid >> 2;       // warp: rows wm*32, cols wn*64
    const int g = lane >> 2, tg = lane & 3;
    const int lr = lane & 7, q = lane >> 3;
    const size_t mBase = (size_t)blockIdx.x * 128;

    const int ar = tid >> 2, aq = tid & 3;       // A: row, 8k-quarter
    const float* aSrc = A + (mBase + ar) * FF + aq * 8;

    auto issue = [&](int kt2) {
        const int slot = kt2 & 3;
        const uint32_t aw = sAraw + (slot * K1_ASLOT + ar * 36 + aq * 8) * 4;
        cpa16(aw,      aSrc + kt2 * 32);
        cpa16(aw + 16, aSrc + kt2 * 32 + 4);
        #pragma unroll
        for (int j = 0; j < 2; j++) {
            const int c = tid * 2 + j;           // 1024 chunks
            const int nrow = c >> 2, cw = (c & 3) * 4;
            cpa16(sBst + (slot * K1_BSLOT + nrow * 20 + cw) * 4,
                  (const char*)g_w1s + ((size_t)kt2 * 4096 + (size_t)c * 4) * 4);
        }
        cp_commit();
    };
    issue(0); issue(1); issue(2);

    float4 acc[2][8];
    #pragma unroll
    for (int i = 0; i < 2; i++)
        #pragma unroll
        for (int j = 0; j < 8; j++) acc[i][j] = make_float4(0.f, 0.f, 0.f, 0.f);

    for (int kt2 = 0; kt2 < 32; kt2++) {
        if (kt2 <= 29) cp_wait2();
        else if (kt2 == 30) cp_wait1();
        else cp_wait0();

        const int slot = kt2 & 3;
        // convert own raw chunk -> bf16 [m][kw] (one ST.128)
        {
            const uint32_t* rw = Araw + slot * K1_ASLOT + ar * 36 + aq * 8;
            const float4 v0 = *(const float4*)rw;
            const float4 v1 = *(const float4*)(rw + 4);
            uint32_t* bf = bfA + (kt2 & 1) * K1_FBUF + ar * 20 + aq * 4;
            *(uint4*)bf = make_uint4(pbf(v0.x, v0.y), pbf(v0.z, v0.w),
                                     pbf(v1.x, v1.y), pbf(v1.z, v1.w));
        }
        __syncthreads();     // publish stage; proves slot (kt2-1)%4 drained
        if (kt2 + 3 < 32) issue(kt2 + 3);

        const uint32_t aBuf = sbfA + ((kt2 & 1) * K1_FBUF) * 4;
        const uint32_t bBuf = sBst + (slot * K1_BSLOT) * 4;
        #pragma unroll
        for (int ks = 0; ks < 2; ks++) {
            uint32_t afr[2][4];
            #pragma unroll
            for (int fm = 0; fm < 2; fm++) {
                const uint32_t ad = aBuf +
                    ((wm * 32 + fm * 16 + lr + (q & 1) * 8) * 20 + ks * 8 + (q >> 1) * 4) * 4;
                ldsm4(afr[fm][0], afr[fm][1], afr[fm][2], afr[fm][3], ad);
            }
            uint32_t bfr[8][2];
            #pragma unroll
            for (int p2 = 0; p2 < 4; p2++) {
                const uint32_t bd = bBuf +
                    ((wn * 64 + (p2 * 2 + (q >> 1)) * 8 + lr) * 20 + ks * 8 + (q & 1) * 4) * 4;
                uint32_t r0, r1, r2, r3;
                ldsm4(r0, r1, r2, r3, bd);
                bfr[p2 * 2][0] = r0;     bfr[p2 * 2][1] = r1;
                bfr[p2 * 2 + 1][0] = r2; bfr[p2 * 2 + 1][1] = r3;
            }
            #pragma unroll
            for (int fn = 0; fn < 8; fn++) {
                mma16(acc[0][fn], afr[0], bfr[fn][0], bfr[fn][1]);
                mma16(acc[1][fn], afr[1], bfr[fn][0], bfr[fn][1]);
            }
        }
    }

    // epilogue: bias+relu -> bf16 g_hb4 [m][128 words]
    uint32_t* hbw = (uint32_t*)g_hb4 + mBase * 128;
    #pragma unroll
    for (int fm = 0; fm < 2; fm++) {
        #pragma unroll
        for (int half = 0; half < 2; half++) {
            const int mloc = wm * 32 + fm * 16 + g + half * 8;
            #pragma unroll
            for (int fn = 0; fn < 8; fn++) {
                const int c = wn * 64 + fn * 8 + tg * 2;
                const float v0 = half ? acc[fm][fn].z : acc[fm][fn].x;
                const float v1 = half ? acc[fm][fn].w : acc[fm][fn].y;
                const float h0 = fmaxf(v0 + bias[c], 0.f);
                const float h1 = fmaxf(v1 + bias[c + 1], 0.f);
                hbw[(size_t)mloc * 128 + (c >> 1)] = pbf(h0, h1);
            }
        }
    }
}

// ============================================================================
// K2: gated-attention logits. CTA 256 tokens, 512 thr, A resident [m][132w],
// B double-buffered [n][36w]; all fragments via ldmatrix.x4.
// ============================================================================
#define K2_LDA   132
#define K2_AW    (256 * K2_LDA)   // 33792 words
#define K2_BSLOT (64 * 36)        // 2304 words per stage
#define K2_SMEM  ((K2_AW + 4 * K2_BSLOT) * 4)   // 172032 B
__global__ __launch_bounds__(512, 1)
void k2_gates(const float* __restrict__ bv, const float* __restrict__ bu,
              const float* __restrict__ ww, const float* __restrict__ bw,
              const unsigned char* __restrict__ mask)
{
    extern __shared__ uint32_t sm2[];
    uint32_t* As  = sm2;                  // [256 m][132]
    uint32_t* BVs = sm2 + K2_AW;          // [2][64 n][36]
    uint32_t* BUs = BVs + 2 * K2_BSLOT;
    __shared__ float red[2][256];
    const uint32_t sA = s2u(As), sBV = s2u(BVs), sBU = s2u(BUs);

    const int tid = threadIdx.x;
    const int lane = tid & 31, wid = tid >> 5;
    const int wm = wid & 7, wn = wid >> 3;       // warp: rows wm*32, cols wn*32
    const int g = lane >> 2, tg = lane & 3;
    const int lr = lane & 7, q = lane >> 3;
    const size_t m0 = (size_t)blockIdx.x * 256;
    const char* aImg = (const char*)g_hb4 + m0 * 512;

    auto fillB = [&](int s, int p) {
        const int c = tid;                        // 512 chunks per matrix
        const int n = c >> 3, cw = (c & 7) * 4;
        const uint32_t d = (p * K2_BSLOT + n * 36 + cw) * 4;
        cpa16(sBV + d, (const char*)g_wvs + ((size_t)s * 2048 + (size_t)c * 4) * 4);
        cpa16(sBU + d, (const char*)g_wus + ((size_t)s * 2048 + (size_t)c * 4) * 4);
    };

    #pragma unroll
    for (int j = 0; j < 16; j++) {
        const int c = j * 512 + tid;              // 8192 chunks
        const int m = c >> 5, cw = (c & 31) * 4;
        cpa16(sA + (m * K2_LDA + cw) * 4, aImg + (size_t)c * 16);
    }
    fillB(0, 0);
    cp_commit();

    float rowsum[4] = {0.f, 0.f, 0.f, 0.f};
    float4 accV[2][4], accU[2][4];

    for (int s = 0; s < 16; s++) {
        const int p = s & 1, nb = s >> 2, kh = s & 3;
        if (s < 15) { fillB(s + 1, p ^ 1); cp_commit(); cp_wait1(); }
        else cp_wait0();
        __syncthreads();

        if (kh == 0) {
            #pragma unroll
            for (int i = 0; i < 2; i++)
                #pragma unroll
                for (int j = 0; j < 4; j++) {
                    accV[i][j] = make_float4(0.f, 0.f, 0.f, 0.f);
                    accU[i][j] = make_float4(0.f, 0.f, 0.f, 0.f);
                }
        }

        const uint32_t vBuf = sBV + (p * K2_BSLOT) * 4;
        const uint32_t uBuf = sBU + (p * K2_BSLOT) * 4;
        #pragma unroll
        for (int ks = 0; ks < 4; ks++) {
            const int kwb = (kh * 4 + ks) * 8;
            uint32_t afr[2][4];
            #pragma unroll
            for (int fm = 0; fm < 2; fm++) {
                const uint32_t ad = sA +
                    ((wm * 32 + fm * 16 + lr + (q & 1) * 8) * K2_LDA + kwb + (q >> 1) * 4) * 4;
                ldsm4(afr[fm][0], afr[fm][1], afr[fm][2], afr[fm][3], ad);
            }
            uint32_t bvf[4][2], buf_[4][2];
            #pragma unroll
            for (int p2 = 0; p2 < 2; p2++) {
                const uint32_t roff =
                    ((wn * 32 + (p2 * 2 + (q >> 1)) * 8 + lr) * 36 + ks * 8 + (q & 1) * 4) * 4;
                uint32_t r0, r1, r2, r3;
                ldsm4(r0, r1, r2, r3, vBuf + roff);
                bvf[p2 * 2][0] = r0;     bvf[p2 * 2][1] = r1;
                bvf[p2 * 2 + 1][0] = r2; bvf[p2 * 2 + 1][1] = r3;
                ldsm4(r0, r1, r2, r3, uBuf + roff);
                buf_[p2 * 2][0] = r0;     buf_[p2 * 2][1] = r1;
                buf_[p2 * 2 + 1][0] = r2; buf_[p2 * 2 + 1][1] = r3;
            }
            #pragma unroll
            for (int fn = 0; fn < 4; fn++) {
                mma16(accV[0][fn], afr[0], bvf[fn][0], bvf[fn][1]);
                mma16(accV[1][fn], afr[1], bvf[fn][0], bvf[fn][1]);
                mma16(accU[0][fn], afr[0], buf_[fn][0], buf_[fn][1]);
                mma16(accU[1][fn], afr[1], buf_[fn][0], buf_[fn][1]);
            }
        }

        if (kh == 3) {
            #pragma unroll
            for (int fm = 0; fm < 2; fm++) {
                #pragma unroll
                for (int fn = 0; fn < 4; fn++) {
                    const int c = nb * 64 + wn * 32 + fn * 8 + tg * 2;
                    const float bv0 = bv[c], bv1 = bv[c + 1];
                    const float bu0 = bu[c], bu1 = bu[c + 1];
                    const float w0 = ww[c],  w1 = ww[c + 1];
                    const float4 av = accV[fm][fn], au = accU[fm][fn];
                    float v, u;
                    v = tanhfast(av.x + bv0); u = 0.5f * tanhfast(0.5f * (au.x + bu0)) + 0.5f;
                    rowsum[fm * 2 + 0] = fmaf(v * u, w0, rowsum[fm * 2 + 0]);
                    v = tanhfast(av.y + bv1); u = 0.5f * tanhfast(0.5f * (au.y + bu1)) + 0.5f;
                    rowsum[fm * 2 + 0] = fmaf(v * u, w1, rowsum[fm * 2 + 0]);
                    v = tanhfast(av.z + bv0); u = 0.5f * tanhfast(0.5f * (au.z + bu0)) + 0.5f;
                    rowsum[fm * 2 + 1] = fmaf(v * u, w0, rowsum[fm * 2 + 1]);
                    v = tanhfast(av.w + bv1); u = 0.5f * tanhfast(0.5f * (au.w + bu1)) + 0.5f;
                    rowsum[fm * 2 + 1] = fmaf(v * u, w1, rowsum[fm * 2 + 1]);
                }
            }
        }
        __syncthreads();
    }

    #pragma unroll
    for (int o = 1; o <= 2; o <<= 1)
        #pragma unroll
        for (int i = 0; i < 4; i++)
            rowsum[i] += __shfl_xor_sync(0xffffffffu, rowsum[i], o);

    if (tg == 0) {
        #pragma unroll
        for (int i = 0; i < 4; i++)
            red[wn][wm * 32 + (i >> 1) * 16 + (i & 1) * 8 + g] = rowsum[i];
    }
    __syncthreads();
    if (tid < 256) {
        const size_t m = m0 + tid;
        float val = red[0][tid] + red[1][tid] + bw[0];
        if (mask[m]) val = -1e30f;
        g_logit[m] = val;
    }
}

// ============================================================================
// K3a: per-batch softmax stats (unchanged).
// ============================================================================
__global__ __launch_bounds__(1024)
void k3a_stats()
{
    __shared__ float sred[1024];
    const int b = blockIdx.x, tid = threadIdx.x;
    const float* lg = g_logit + (size_t)b * TT;

    float lmax = -FLT_MAX;
    #pragma unroll
    for (int i = 0; i < 8; i++) lmax = fmaxf(lmax, lg[tid + i * 1024]);
    sred[tid] = lmax;
    __syncthreads();
    for (int s = 512; s > 0; s >>= 1) {
        if (tid < s) sred[tid] = fmaxf(sred[tid], sred[tid + s]);
        __syncthreads();
    }
    const float mx = sred[0];
    __syncthreads();

    float lsum = 0.f;
    #pragma unroll
    for (int i = 0; i < 8; i++) lsum += __expf(lg[tid + i * 1024] - mx);
    sred[tid] = lsum;
    __syncthreads();
    for (int s = 512; s > 0; s >>= 1) {
        if (tid < s) sred[tid] += sred[tid + s];
        __syncthreads();
    }
    if (tid == 0) g_stat[b] = make_float2(mx, 1.f / sred[0]);
}

// ============================================================================
// K3b: partial pooling from plain bf16 g_hb4 [m][128w]. grid (64, 8) x 256.
// smem tile [t 128][132w]; thread (cw, mh) accumulates 2 cols over 64 tokens.
// ============================================================================
#define K3B_LDH 132
#define K3B_SMEM (128 * K3B_LDH * 4)   // 67584 B
__global__ __launch_bounds__(256)
void k3b_pool()
{
    extern __shared__ uint32_t sh[];
    __shared__ float w[128];
    __shared__ float prt[256];
    const int b = blockIdx.y, ch = blockIdx.x, tid = threadIdx.x;
    const char* src = (const char*)g_hb4 + (size_t)(b * TT + ch * 128) * 512;
    const uint32_t sbase = s2u(sh);

    #pragma unroll
    for (int j = 0; j < 16; j++) {
        const int c = j * 256 + tid;                   // 4096 chunks
        const int t = c >> 5, cw = (c & 31) * 4;
        cpa16(sbase + (t * K3B_LDH + cw) * 4, src + (size_t)c * 16);
    }
    cp_commit();

    const float2 st = g_stat[b];
    if (tid < 128)
        w[tid] = __expf(g_logit[(size_t)b * TT + ch * 128 + tid] - st.x) * st.y;
    cp_wait0();
    __syncthreads();

    const int cw = tid & 127, mh = tid >> 7;
    float alo = 0.f, ahi = 0.f;
    #pragma unroll 8
    for (int j = 0; j < 64; j++) {
        const int t = mh * 64 + j;
        const uint32_t u = sh[t * K3B_LDH + cw];
        const float wt = w[t];
        alo = fmaf(wt, __uint_as_float(u << 16), alo);
        ahi = fmaf(wt, __uint_as_float(u & 0xFFFF0000u), ahi);
    }
    if (mh == 1) { prt[cw * 2] = alo; prt[cw * 2 + 1] = ahi; }
    __syncthreads();
    if (mh == 0) {
        float* dst = &g_part[((size_t)b * 64 + ch) * 256 + cw * 2];
        dst[0] = alo + prt[cw * 2];
        dst[1] = ahi + prt[cw * 2 + 1];
    }
}

// ============================================================================
// k3c_final: reduce 64 partials -> slide -> output logits (fused). grid = 8.
// ============================================================================
__global__ __launch_bounds__(256)
void k3c_final(const float* __restrict__ Wc, const float* __restrict__ bc,
               float* __restrict__ out)
{
    __shared__ float sred[256];
    const int b = blockIdx.x, tid = threadIdx.x;
    float s = 0.f;
    #pragma unroll 8
    for (int j = 0; j < 64; j++) s += g_part[((size_t)b * 64 + j) * 256 + tid];
    sred[tid] = s;
    __syncthreads();
    const int wid = tid >> 5, lane = tid & 31;
    if (wid < 2) {
        float d = 0.f;
        for (int c = lane; c < 256; c += 32) d = fmaf(sred[c], Wc[c * OO + wid], d);
        #pragma unroll
        for (int off = 16; off > 0; off >>= 1) d += __shfl_down_sync(0xffffffffu, d, off);
        if (lane == 0) out[b * OO + wid] = d + bc[wid];
    }
}

// ============================================================================
extern "C" void kernel_launch(void* const* d_in, const int* in_sizes, int n_in,
                              void* d_out, int out_size)
{
    const float*         bags = (const float*)d_in[0];
    const unsigned char* mask = (const unsigned char*)d_in[1];
    const float*         W1   = (const float*)d_in[2];
    const float*         b1   = (const float*)d_in[3];
    const float*         Wv   = (const float*)d_in[4];
    const float*         bv   = (const float*)d_in[5];
    const float*         Wu   = (const float*)d_in[6];
    const float*         bu   = (const float*)d_in[7];
    const float*         ww   = (const float*)d_in[8];
    const float*         bw   = (const float*)d_in[9];
    const float*         Wc   = (const float*)d_in[10];
    const float*         bc   = (const float*)d_in[11];
    float*               out  = (float*)d_out;

    cudaFuncSetAttribute(k1_gemm_relu, cudaFuncAttributeMaxDynamicSharedMemorySize, K1_SMEM);
    cudaFuncSetAttribute(k2_gates,     cudaFuncAttributeMaxDynamicSharedMemorySize, K2_SMEM);
    cudaFuncSetAttribute(k3b_pool,     cudaFuncAttributeMaxDynamicSharedMemorySize, K3B_SMEM);

    k1pre<<<32, 256>>>(W1);
    k2pre<<<16, 256>>>(Wv, Wu);
    k1_gemm_relu<<<MTOK / 128, 512, K1_SMEM>>>(bags, b1);
    k2_gates<<<MTOK / 256, 512, K2_SMEM>>>(bv, bu, ww, bw, mask);
    k3a_stats<<<BSZ, 1024>>>();
    k3b_pool<<<dim3(NCHUNK, BSZ), 256, K3B_SMEM>>>();
    k3c_final<<<BSZ, 256>>>(Wc, bc, out);
}

// round 13
// speedup vs baseline: 1.0461x; 1.0461x over previous
#include <cuda_runtime.h>
#include <math.h>
#include <stdint.h>
#include <float.h>

#define BSZ 8
#define TT  8192
#define FF  1024
#define HH  256
#define OO  2
#define MTOK (BSZ * TT)   // 65536 tokens
#define NCHUNK 64

// ---- scratch (static device globals; no runtime allocation) ----
__device__ uint4  g_hb4[(size_t)MTOK * 32];   // 32 MB bf16 h, layout [mblk 512][kp 128][m 128]
__device__ float  g_logit[MTOK];
__device__ float2 g_stat[BSZ];
__device__ float  g_part[BSZ * NCHUNK * HH];
__device__ uint4  g_w1s[64 * 512];            // 512 KB: W1 bf16 [kt 64][kp 8][n 256]
__device__ uint4  g_wvs[16 * 512];            // 128 KB: Wv bf16 [blk 16][kp 32][n 64]
__device__ uint4  g_wus[16 * 512];            // 128 KB: Wu

// ---- helpers ----
__device__ __forceinline__ uint32_t pbf(float lo, float hi) {
    uint32_t r; asm("cvt.rn.bf16x2.f32 %0, %1, %2;" : "=r"(r) : "f"(hi), "f"(lo)); return r;
}
__device__ __forceinline__ float tanhfast(float x) {
    float y; asm("tanh.approx.f32 %0, %1;" : "=f"(y) : "f"(x)); return y;
}
__device__ __forceinline__ void mma16(float4& d, const uint32_t* a, uint32_t b0, uint32_t b1) {
    asm volatile("mma.sync.aligned.m16n8k16.row.col.f32.bf16.bf16.f32 "
        "{%0,%1,%2,%3}, {%4,%5,%6,%7}, {%8,%9}, {%0,%1,%2,%3};"
        : "+f"(d.x), "+f"(d.y), "+f"(d.z), "+f"(d.w)
        : "r"(a[0]), "r"(a[1]), "r"(a[2]), "r"(a[3]), "r"(b0), "r"(b1));
}
__device__ __forceinline__ uint32_t s2u(const void* p) {
    uint32_t a; asm("{ .reg .u64 t; cvta.to.shared.u64 t, %1; cvt.u32.u64 %0, t; }" : "=r"(a) : "l"(p));
    return a;
}
__device__ __forceinline__ void cpa16(uint32_t dst, const void* src) {
    asm volatile("cp.async.cg.shared.global [%0], [%1], 16;" :: "r"(dst), "l"(src));
}
__device__ __forceinline__ void cp_commit() { asm volatile("cp.async.commit_group;"); }
__device__ __forceinline__ void cp_wait0()  { asm volatile("cp.async.wait_group 0;"); }
__device__ __forceinline__ void cp_wait1()  { asm volatile("cp.async.wait_group 1;"); }

// ============================================================================
// kpre: merged weight pre-conversion.
//  blocks 0..63  : W1 -> g_w1s [kt 64][kp 8][n 256]
//  blocks 64..79 : Wv/Wu -> g_wvs/g_wus [blk 16][kp 32][n 64]
// ============================================================================
__global__ __launch_bounds__(256)
void kpre(const float* __restrict__ W1, const float* __restrict__ Wv,
          const float* __restrict__ Wu)
{
    const int tid = threadIdx.x;
    if (blockIdx.x < 64) {
        const int kt = blockIdx.x;
        const int kp = tid >> 5, n8 = (tid & 31) << 3;
        const float* r0 = W1 + (size_t)(kt * 16 + 2 * kp) * HH + n8;
        const float4 a0 = *(const float4*)(r0),        a1 = *(const float4*)(r0 + 4);
        const float4 b0 = *(const float4*)(r0 + HH),   b1 = *(const float4*)(r0 + HH + 4);
        g_w1s[kt * 512 + kp * 64 + (n8 >> 2)] =
            make_uint4(pbf(a0.x, b0.x), pbf(a0.y, b0.y), pbf(a0.z, b0.z), pbf(a0.w, b0.w));
        g_w1s[kt * 512 + kp * 64 + (n8 >> 2) + 1] =
            make_uint4(pbf(a1.x, b1.x), pbf(a1.y, b1.y), pbf(a1.z, b1.z), pbf(a1.w, b1.w));
    } else {
        const int blk = blockIdx.x - 64;
        const int nb = blk >> 2, kh = blk & 3;
        const int kp = tid >> 3, n8 = (tid & 7) << 3;
        const size_t off = (size_t)(kh * 64 + 2 * kp) * HH + nb * 64 + n8;
        {
            const float4 a0 = *(const float4*)(Wv + off),      a1 = *(const float4*)(Wv + off + 4);
            const float4 b0 = *(const float4*)(Wv + off + HH), b1 = *(const float4*)(Wv + off + HH + 4);
            g_wvs[blk * 512 + kp * 16 + (n8 >> 2)] =
                make_uint4(pbf(a0.x, b0.x), pbf(a0.y, b0.y), pbf(a0.z, b0.z), pbf(a0.w, b0.w));
            g_wvs[blk * 512 + kp * 16 + (n8 >> 2) + 1] =
                make_uint4(pbf(a1.x, b1.x), pbf(a1.y, b1.y), pbf(a1.z, b1.z), pbf(a1.w, b1.w));
        }
        {
            const float4 a0 = *(const float4*)(Wu + off),      a1 = *(const float4*)(Wu + off + 4);
            const float4 b0 = *(const float4*)(Wu + off + HH), b1 = *(const float4*)(Wu + off + HH + 4);
            g_wus[blk * 512 + kp * 16 + (n8 >> 2)] =
                make_uint4(pbf(a0.x, b0.x), pbf(a0.y, b0.y), pbf(a0.z, b0.z), pbf(a0.w, b0.w));
            g_wus[blk * 512 + kp * 16 + (n8 >> 2) + 1] =
                make_uint4(pbf(a1.x, b1.x), pbf(a1.y, b1.y), pbf(a1.z, b1.z), pbf(a1.w, b1.w));
        }
    }
}

// ============================================================================
// K1: h = relu(bags @ W1 + b1). M=64 tiles (grid 1024), 256 thr, 2 CTAs/SM.
// K=32 stages, 3-slot depth-2 cp.async. A raw fp32 -> bf16 [kp 16][72]
// (72 = 8 mod 32 -> conflict-free fragment reads), B [kp 16][264].
// Epilogue -> blocked bf16 g_hb4 [mblk 512][kp 128][m 128].
// ============================================================================
#define K1_ASLOT (64 * 36)      // 2304 raw A words / slot
#define K1_BSLOT (16 * 264)     // 4224 B words / slot
#define K1_FBUF  (16 * 72)      // 1152 bf16 A words / buffer
#define K1_SMEM  ((3 * K1_ASLOT + 3 * K1_BSLOT + 2 * K1_FBUF) * 4)   // 87552 B
__global__ __launch_bounds__(256, 2)
void k1_gemm_relu(const float* __restrict__ A, const float* __restrict__ bias)
{
    extern __shared__ uint32_t sm1[];
    uint32_t* Araw = sm1;                       // [3][64][36] raw fp32
    uint32_t* Bst  = sm1 + 3 * K1_ASLOT;        // [3][16][264] bf16 pairs
    uint32_t* bfA  = Bst + 3 * K1_BSLOT;        // [2][16][72] bf16 pairs
    const uint32_t sAraw = s2u(Araw), sBst = s2u(Bst);

    const int tid = threadIdx.x;
    const int lane = tid & 31, wid = tid >> 5;
    const int wm = wid & 1, wn = wid >> 1;       // warp: rows wm*32, cols wn*64
    const int g = lane >> 2, tg = lane & 3;
    const size_t mBase = (size_t)blockIdx.x * 64;

    const int ar = tid >> 2, aq = tid & 3;       // A: row 0..63, 8k-quarter
    const float* aSrc = A + (mBase + ar) * FF + aq * 8;

    auto issue = [&](int kt2) {
        const int slot = kt2 - (kt2 / 3) * 3;    // kt2 % 3
        const uint32_t aw = sAraw + (slot * K1_ASLOT + ar * 36 + aq * 8) * 4;
        cpa16(aw,      aSrc + kt2 * 32);
        cpa16(aw + 16, aSrc + kt2 * 32 + 4);
        #pragma unroll
        for (int j = 0; j < 2; j++) {
            const int c = tid * 2 + j;           // 512 chunks per k16 image
            const int row = c >> 6, col = (c & 63) << 2;
            cpa16(sBst + (slot * K1_BSLOT + row * 264 + col) * 4,
                  (const char*)g_w1s + (size_t)(2 * kt2) * 8192 + (size_t)c * 16);
            cpa16(sBst + (slot * K1_BSLOT + (8 + row) * 264 + col) * 4,
                  (const char*)g_w1s + (size_t)(2 * kt2 + 1) * 8192 + (size_t)c * 16);
        }
        cp_commit();
    };
    issue(0); issue(1);

    float4 acc[2][8];
    #pragma unroll
    for (int i = 0; i < 2; i++)
        #pragma unroll
        for (int j = 0; j < 8; j++) acc[i][j] = make_float4(0.f, 0.f, 0.f, 0.f);

    for (int kt2 = 0; kt2 < 32; kt2++) {
        if (kt2 < 31) cp_wait1();
        else cp_wait0();

        const int slot = kt2 - (kt2 / 3) * 3;
        // convert own raw chunk -> bf16 [kp 16][72]
        {
            const uint32_t* rw = Araw + slot * K1_ASLOT + ar * 36 + aq * 8;
            const float4 v0 = *(const float4*)rw;
            const float4 v1 = *(const float4*)(rw + 4);
            uint32_t* bf = bfA + (kt2 & 1) * K1_FBUF;
            bf[(aq * 4 + 0) * 72 + ar] = pbf(v0.x, v0.y);
            bf[(aq * 4 + 1) * 72 + ar] = pbf(v0.z, v0.w);
            bf[(aq * 4 + 2) * 72 + ar] = pbf(v1.x, v1.y);
            bf[(aq * 4 + 3) * 72 + ar] = pbf(v1.z, v1.w);
        }
        __syncthreads();     // publish stage; proves slot (kt2-1)%3 readers done
        if (kt2 + 2 < 32) issue(kt2 + 2);   // slot (kt2+2)%3 == (kt2-1)%3: safe

        const uint32_t* ap = bfA + (kt2 & 1) * K1_FBUF;
        const uint32_t* bp = Bst + slot * K1_BSLOT;
        #pragma unroll
        for (int s = 0; s < 2; s++) {
            const int r0 = s * 8 + tg, r1 = s * 8 + tg + 4;
            uint32_t afr[2][4];
            #pragma unroll
            for (int fm = 0; fm < 2; fm++) {
                const int m = wm * 32 + fm * 16 + g;
                afr[fm][0] = ap[r0 * 72 + m];  afr[fm][1] = ap[r0 * 72 + m + 8];
                afr[fm][2] = ap[r1 * 72 + m];  afr[fm][3] = ap[r1 * 72 + m + 8];
            }
            #pragma unroll
            for (int fn = 0; fn < 8; fn++) {
                const int n = wn * 64 + fn * 8 + g;
                const uint32_t b0 = bp[r0 * 264 + n], b1 = bp[r1 * 264 + n];
                mma16(acc[0][fn], afr[0], b0, b1);
                mma16(acc[1][fn], afr[1], b0, b1);
            }
        }
    }

    // epilogue: bias+relu -> blocked bf16 g_hb4 ([mblk][kp 128][m 128])
    uint32_t* hbw = (uint32_t*)g_hb4 + (size_t)(blockIdx.x >> 1) * 16384;
    const int mOff = (blockIdx.x & 1) * 64;
    #pragma unroll
    for (int fm = 0; fm < 2; fm++) {
        #pragma unroll
        for (int half = 0; half < 2; half++) {
            const int mloc = mOff + wm * 32 + fm * 16 + g + half * 8;
            #pragma unroll
            for (int fn = 0; fn < 8; fn++) {
                const int c = wn * 64 + fn * 8 + tg * 2;
                const float v0 = half ? acc[fm][fn].z : acc[fm][fn].x;
                const float v1 = half ? acc[fm][fn].w : acc[fm][fn].y;
                const float h0 = fmaxf(v0 + bias[c], 0.f);
                const float h1 = fmaxf(v1 + bias[c + 1], 0.f);
                hbw[(c >> 1) * 128 + mloc] = pbf(h0, h1);
            }
        }
    }
}

// ============================================================================
// K2 (R11-proven): CTA 256 tokens, 512 thr, A resident [kp 128][264],
// B double-buffered [kp 32][72].
// ============================================================================
#define K2_LDA 264
#define K2_AW  (128 * K2_LDA)   // 33792 words (132 KB)
#define K2_BW  (32 * 72)        // 2304 words per stage
#define K2_SMEM ((K2_AW + 4 * K2_BW) * 4)   // 172032 B
__global__ __launch_bounds__(512, 1)
void k2_gates(const float* __restrict__ bv, const float* __restrict__ bu,
              const float* __restrict__ ww, const float* __restrict__ bw,
              const unsigned char* __restrict__ mask)
{
    extern __shared__ uint32_t sm2[];
    uint32_t* As  = sm2;                  // [128 kp][264]
    uint32_t* BVs = sm2 + K2_AW;          // [2][32][72]
    uint32_t* BUs = BVs + 2 * K2_BW;
    __shared__ float red[2][256];
    const uint32_t sA = s2u(As), sBV = s2u(BVs), sBU = s2u(BUs);

    const int tid = threadIdx.x;
    const int lane = tid & 31, wid = tid >> 5;
    const int wm = wid & 7, wn = wid >> 3;       // warp: rows wm*32, cols wn*32
    const int g = lane >> 2, tg = lane & 3;
    const size_t m0 = (size_t)blockIdx.x * 256;
    const char* aImg = (const char*)g_hb4 + (size_t)(2 * blockIdx.x) * 65536;

    auto fillB = [&](int s, int p) {
        const int c = tid;
        const int row = c >> 4, col = c & 15;
        const uint32_t d = p * (K2_BW * 4) + row * (72 * 4) + col * 16;
        cpa16(sBV + d, (const char*)g_wvs + (size_t)s * 8192 + (size_t)c * 16);
        cpa16(sBU + d, (const char*)g_wus + (size_t)s * 8192 + (size_t)c * 16);
    };

    #pragma unroll
    for (int j = 0; j < 16; j++) {
        const int c = j * 512 + tid;
        const int q = c >> 12, r = c & 4095;
        const int kp = r >> 5, mw = (r & 31) << 2;
        cpa16(sA + (kp * K2_LDA + q * 128 + mw) * 4, aImg + (size_t)c * 16);
    }
    fillB(0, 0);
    cp_commit();

    float rowsum[4] = {0.f, 0.f, 0.f, 0.f};
    float4 accV[2][4], accU[2][4];

    for (int s = 0; s < 16; s++) {
        const int p = s & 1, nb = s >> 2, kh = s & 3;
        if (s < 15) { fillB(s + 1, p ^ 1); cp_commit(); cp_wait1(); }
        else cp_wait0();
        __syncthreads();

        if (kh == 0) {
            #pragma unroll
            for (int i = 0; i < 2; i++)
                #pragma unroll
                for (int j = 0; j < 4; j++) {
                    accV[i][j] = make_float4(0.f, 0.f, 0.f, 0.f);
                    accU[i][j] = make_float4(0.f, 0.f, 0.f, 0.f);
                }
        }

        const uint32_t* vp = BVs + p * K2_BW;
        const uint32_t* up = BUs + p * K2_BW;
        #pragma unroll
        for (int ks = 0; ks < 4; ks++) {
            const int r = ks * 8 + tg;
            const int ra = kh * 32 + r;
            uint32_t afr[2][4];
            #pragma unroll
            for (int fm = 0; fm < 2; fm++) {
                const int m = wm * 32 + fm * 16 + g;
                afr[fm][0] = As[ra * K2_LDA + m];       afr[fm][1] = As[ra * K2_LDA + m + 8];
                afr[fm][2] = As[(ra + 4) * K2_LDA + m]; afr[fm][3] = As[(ra + 4) * K2_LDA + m + 8];
            }
            #pragma unroll
            for (int fn = 0; fn < 4; fn++) {
                const int n = wn * 32 + fn * 8 + g;
                const uint32_t v0 = vp[r * 72 + n], v1 = vp[(r + 4) * 72 + n];
                const uint32_t u0 = up[r * 72 + n], u1 = up[(r + 4) * 72 + n];
                mma16(accV[0][fn], afr[0], v0, v1);
                mma16(accV[1][fn], afr[1], v0, v1);
                mma16(accU[0][fn], afr[0], u0, u1);
                mma16(accU[1][fn], afr[1], u0, u1);
            }
        }

        if (kh == 3) {
            #pragma unroll
            for (int fm = 0; fm < 2; fm++) {
                #pragma unroll
                for (int fn = 0; fn < 4; fn++) {
                    const int c = nb * 64 + wn * 32 + fn * 8 + tg * 2;
                    const float bv0 = bv[c], bv1 = bv[c + 1];
                    const float bu0 = bu[c], bu1 = bu[c + 1];
                    const float w0 = ww[c],  w1 = ww[c + 1];
                    const float4 av = accV[fm][fn], au = accU[fm][fn];
                    float v, u;
                    v = tanhfast(av.x + bv0); u = 0.5f * tanhfast(0.5f * (au.x + bu0)) + 0.5f;
                    rowsum[fm * 2 + 0] = fmaf(v * u, w0, rowsum[fm * 2 + 0]);
                    v = tanhfast(av.y + bv1); u = 0.5f * tanhfast(0.5f * (au.y + bu1)) + 0.5f;
                    rowsum[fm * 2 + 0] = fmaf(v * u, w1, rowsum[fm * 2 + 0]);
                    v = tanhfast(av.z + bv0); u = 0.5f * tanhfast(0.5f * (au.z + bu0)) + 0.5f;
                    rowsum[fm * 2 + 1] = fmaf(v * u, w0, rowsum[fm * 2 + 1]);
                    v = tanhfast(av.w + bv1); u = 0.5f * tanhfast(0.5f * (au.w + bu1)) + 0.5f;
                    rowsum[fm * 2 + 1] = fmaf(v * u, w1, rowsum[fm * 2 + 1]);
                }
            }
        }
        __syncthreads();
    }

    #pragma unroll
    for (int o = 1; o <= 2; o <<= 1)
        #pragma unroll
        for (int i = 0; i < 4; i++)
            rowsum[i] += __shfl_xor_sync(0xffffffffu, rowsum[i], o);

    if (tg == 0) {
        #pragma unroll
        for (int i = 0; i < 4; i++)
            red[wn][wm * 32 + (i >> 1) * 16 + (i & 1) * 8 + g] = rowsum[i];
    }
    __syncthreads();
    if (tid < 256) {
        const size_t m = m0 + tid;
        float val = red[0][tid] + red[1][tid] + bw[0];
        if (mask[m]) val = -1e30f;
        g_logit[m] = val;
    }
}

// ============================================================================
// K3a: per-batch softmax stats.
// ============================================================================
__global__ __launch_bounds__(1024)
void k3a_stats()
{
    __shared__ float sred[1024];
    const int b = blockIdx.x, tid = threadIdx.x;
    const float* lg = g_logit + (size_t)b * TT;

    float lmax = -FLT_MAX;
    #pragma unroll
    for (int i = 0; i < 8; i++) lmax = fmaxf(lmax, lg[tid + i * 1024]);
    sred[tid] = lmax;
    __syncthreads();
    for (int s = 512; s > 0; s >>= 1) {
        if (tid < s) sred[tid] = fmaxf(sred[tid], sred[tid + s]);
        __syncthreads();
    }
    const float mx = sred[0];
    __syncthreads();

    float lsum = 0.f;
    #pragma unroll
    for (int i = 0; i < 8; i++) lsum += __expf(lg[tid + i * 1024] - mx);
    sred[tid] = lsum;
    __syncthreads();
    for (int s = 512; s > 0; s >>= 1) {
        if (tid < s) sred[tid] += sred[tid + s];
        __syncthreads();
    }
    if (tid == 0) g_stat[b] = make_float2(mx, 1.f / sred[0]);
}

// ============================================================================
// K3b: partial pooling from blocked bf16 g_hb4. grid (64, 8) x 256.
// Stage [kp 128][132] smem tile via cp.async; thread (kp, mh) does 2 cols.
// ============================================================================
#define K3B_LDH 132
#define K3B_SMEM (128 * K3B_LDH * 4)   // 67584 B
__global__ __launch_bounds__(256)
void k3b_pool()
{
    extern __shared__ uint32_t sh[];
    __shared__ float w[128];
    __shared__ float prt[256];
    const int b = blockIdx.y, ch = blockIdx.x, tid = threadIdx.x;
    const char* src = (const char*)g_hb4 + (size_t)(b * 64 + ch) * 65536;
    const uint32_t sbase = s2u(sh);

    #pragma unroll
    for (int j = 0; j < 16; j++) {
        const int c = j * 256 + tid;                   // 4096 uint4 chunks
        const int kp = c >> 5, mw = (c & 31) << 2;
        cpa16(sbase + (kp * K3B_LDH + mw) * 4, src + (size_t)c * 16);
    }
    cp_commit();

    const float2 st = g_stat[b];
    if (tid < 128)
        w[tid] = __expf(g_logit[(size_t)b * TT + ch * 128 + tid] - st.x) * st.y;
    cp_wait0();
    __syncthreads();

    const int kp = tid & 127, mh = tid >> 7;
    const uint32_t* row = sh + kp * K3B_LDH + mh * 64;
    const float* wp = &w[mh * 64];
    float alo = 0.f, ahi = 0.f;
    #pragma unroll
    for (int j = 0; j < 16; j++) {
        const uint4 u = *(const uint4*)(row + j * 4);
        const float w0 = wp[j * 4 + 0], w1 = wp[j * 4 + 1];
        const float w2 = wp[j * 4 + 2], w3 = wp[j * 4 + 3];
        alo = fmaf(w0, __uint_as_float(u.x << 16), alo);
        ahi = fmaf(w0, __uint_as_float(u.x & 0xFFFF0000u), ahi);
        alo = fmaf(w1, __uint_as_float(u.y << 16), alo);
        ahi = fmaf(w1, __uint_as_float(u.y & 0xFFFF0000u), ahi);
        alo = fmaf(w2, __uint_as_float(u.z << 16), alo);
        ahi = fmaf(w2, __uint_as_float(u.z & 0xFFFF0000u), ahi);
        alo = fmaf(w3, __uint_as_float(u.w << 16), alo);
        ahi = fmaf(w3, __uint_as_float(u.w & 0xFFFF0000u), ahi);
    }
    if (mh == 1) { prt[kp * 2] = alo; prt[kp * 2 + 1] = ahi; }
    __syncthreads();
    if (mh == 0) {
        float* dst = &g_part[((size_t)b * 64 + ch) * 256 + kp * 2];
        dst[0] = alo + prt[kp * 2];
        dst[1] = ahi + prt[kp * 2 + 1];
    }
}

// ============================================================================
// k3c_final: reduce 64 partials -> slide -> output logits (fused). grid = 8.
// ============================================================================
__global__ __launch_bounds__(256)
void k3c_final(const float* __restrict__ Wc, const float* __restrict__ bc,
               float* __restrict__ out)
{
    __shared__ float sred[256];
    const int b = blockIdx.x, tid = threadIdx.x;
    float s = 0.f;
    #pragma unroll 8
    for (int j = 0; j < 64; j++) s += g_part[((size_t)b * 64 + j) * 256 + tid];
    sred[tid] = s;
    __syncthreads();
    const int wid = tid >> 5, lane = tid & 31;
    if (wid < 2) {
        float d = 0.f;
        for (int c = lane; c < 256; c += 32) d = fmaf(sred[c], Wc[c * OO + wid], d);
        #pragma unroll
        for (int off = 16; off > 0; off >>= 1) d += __shfl_down_sync(0xffffffffu, d, off);
        if (lane == 0) out[b * OO + wid] = d + bc[wid];
    }
}

// ============================================================================
extern "C" void kernel_launch(void* const* d_in, const int* in_sizes, int n_in,
                              void* d_out, int out_size)
{
    const float*         bags = (const float*)d_in[0];
    const unsigned char* mask = (const unsigned char*)d_in[1];
    const float*         W1   = (const float*)d_in[2];
    const float*         b1   = (const float*)d_in[3];
    const float*         Wv   = (const float*)d_in[4];
    const float*         bv   = (const float*)d_in[5];
    const float*         Wu   = (const float*)d_in[6];
    const float*         bu   = (const float*)d_in[7];
    const float*         ww   = (const float*)d_in[8];
    const float*         bw   = (const float*)d_in[9];
    const float*         Wc   = (const float*)d_in[10];
    const float*         bc   = (const float*)d_in[11];
    float*               out  = (float*)d_out;

    cudaFuncSetAttribute(k1_gemm_relu, cudaFuncAttributeMaxDynamicSharedMemorySize, K1_SMEM);
    cudaFuncSetAttribute(k2_gates,     cudaFuncAttributeMaxDynamicSharedMemorySize, K2_SMEM);
    cudaFuncSetAttribute(k3b_pool,     cudaFuncAttributeMaxDynamicSharedMemorySize, K3B_SMEM);

    kpre<<<80, 256>>>(W1, Wv, Wu);
    k1_gemm_relu<<<MTOK / 64, 256, K1_SMEM>>>(bags, b1);
    k2_gates<<<MTOK / 256, 512, K2_SMEM>>>(bv, bu, ww, bw, mask);
    k3a_stats<<<BSZ, 1024>>>();
    k3b_pool<<<dim3(NCHUNK, BSZ), 256, K3B_SMEM>>>();
    k3c_final<<<BSZ, 256>>>(Wc, bc, out);
}